// round 14
// baseline (speedup 1.0000x reference)
#include <cuda_runtime.h>
#include <cuda_bf16.h>
#include <cstdint>

constexpr int B = 2, L = 2048, D = 1024, H = 16;
constexpr int M = B * L;
constexpr int OUT_ELEMS = B * L * D;

// ---- static device scratch ----
__device__ __align__(16) __nv_bfloat16 g_qh[M * D], g_ql[M * D];
__device__ __align__(16) __nv_bfloat16 g_kh[M * D], g_kl[M * D], g_vbf[M * D];
__device__ __align__(16) __nv_bfloat16 g_wqh[D * D], g_wql[D * D];
__device__ __align__(16) __nv_bfloat16 g_wkh[D * D], g_wkl[D * D];
__device__ __align__(16) __nv_bfloat16 g_wvh[D * D], g_wfh[D * D];
__device__ __align__(16) __nv_bfloat16 g_Qh[M * D], g_Ql[M * D];
__device__ __align__(16) __nv_bfloat16 g_Kh[M * D], g_Kl[M * D];
__device__ __align__(16) __nv_bfloat16 g_Vt[M * D];   // (b,h,dv,l)
__device__ __align__(16) __nv_bfloat16 g_Obf[M * D];  // (b,l,h*dv)
__device__ __align__(16) float g_X[M * D];
__device__ uint32_t g_mbits[(size_t)B * L * (L / 32)];

// ---- helpers ----
__device__ __forceinline__ uint32_t s2u(const void* p) {
  uint32_t a;
  asm("{ .reg .u64 t; cvta.to.shared.u64 t, %1; cvt.u32.u64 %0, t; }" : "=r"(a) : "l"(p));
  return a;
}
#define CPA(dst, src) asm volatile("cp.async.cg.shared.global [%0], [%1], 16;" :: "r"(dst), "l"(src))
#define CPC() asm volatile("cp.async.commit_group;" ::: "memory")
#define CPW(n) asm volatile("cp.async.wait_group %0;" :: "n"(n) : "memory")
__device__ __forceinline__ void ldm4(uint32_t* r, uint32_t a) {
  asm volatile("ldmatrix.sync.aligned.m8n8.x4.shared.b16 {%0,%1,%2,%3}, [%4];"
               : "=r"(r[0]), "=r"(r[1]), "=r"(r[2]), "=r"(r[3]) : "r"(a));
}
__device__ __forceinline__ void mma_bf(float* d, const uint32_t* a, const uint32_t* b) {
  asm volatile(
      "mma.sync.aligned.m16n8k16.row.col.f32.bf16.bf16.f32 "
      "{%0,%1,%2,%3},{%4,%5,%6,%7},{%8,%9},{%0,%1,%2,%3};"
      : "+f"(d[0]), "+f"(d[1]), "+f"(d[2]), "+f"(d[3])
      : "r"(a[0]), "r"(a[1]), "r"(a[2]), "r"(a[3]), "r"(b[0]), "r"(b[1]));
}
__device__ __forceinline__ uint32_t packbf(float a, float b) {
  __nv_bfloat162 p = __halves2bfloat162(__float2bfloat16(a), __float2bfloat16(b));
  return *(uint32_t*)&p;
}

// ---- merged prep kernel ----
__global__ void __launch_bounds__(256) prep(const float* __restrict__ q,
                                            const float* __restrict__ k,
                                            const float* __restrict__ v,
                                            const float* __restrict__ wq,
                                            const float* __restrict__ wk,
                                            const float* __restrict__ wv,
                                            const float* __restrict__ wfc,
                                            const int* __restrict__ mask,
                                            uint32_t* __restrict__ bits) {
  const int blk = blockIdx.x;
  if (blk < 12288) {
    const int z = blk >> 12;
    const int lb = blk & 4095;
    size_t i = (size_t)lb * 1024 + threadIdx.x * 4;
    const float* in = (z == 0) ? q : (z == 1) ? k : v;
    float4 vv = *(const float4*)(in + i);
    if (z == 2) {
      *(uint2*)(g_vbf + i) = make_uint2(packbf(vv.x, vv.y), packbf(vv.z, vv.w));
      return;
    }
    __nv_bfloat16* hi = (z == 0) ? g_qh : g_kh;
    __nv_bfloat16* lo = (z == 0) ? g_ql : g_kl;
    float a[4] = {vv.x, vv.y, vv.z, vv.w};
    uint32_t ph[2], pl[2];
#pragma unroll
    for (int j = 0; j < 2; j++) {
      float x0 = a[j * 2], x1 = a[j * 2 + 1];
      __nv_bfloat16 h0 = __float2bfloat16(x0), h1 = __float2bfloat16(x1);
      ph[j] = packbf(x0, x1);
      pl[j] = packbf(x0 - __bfloat162float(h0), x1 - __bfloat162float(h1));
    }
    *(uint2*)(hi + i) = make_uint2(ph[0], ph[1]);
    *(uint2*)(lo + i) = make_uint2(pl[0], pl[1]);
  } else if (blk < 16384) {
    const int bw = blk - 12288;
    const int z = bw >> 10;
    const int lb = bw & 1023;
    const float* w = (z == 0) ? wq : (z == 1) ? wk : (z == 2) ? wv : wfc;
    __nv_bfloat16* th = (z == 0) ? g_wqh : (z == 1) ? g_wkh : (z == 2) ? g_wvh : g_wfh;
    __nv_bfloat16* tl = (z == 0) ? g_wql : (z == 1) ? g_wkl : nullptr;
    __shared__ float t[32][33];
    int tx = threadIdx.x & 31, ty = threadIdx.x >> 5;
    int x0 = (lb & 31) * 32, y0 = (lb >> 5) * 32;
#pragma unroll
    for (int i = 0; i < 4; i++)
      t[ty + i * 8][tx] = w[(size_t)(y0 + ty + i * 8) * D + x0 + tx];
    __syncthreads();
#pragma unroll
    for (int i = 0; i < 4; i++) {
      float vv = t[tx][ty + i * 8];
      __nv_bfloat16 h = __float2bfloat16(vv);
      size_t o = (size_t)(x0 + ty + i * 8) * D + y0 + tx;
      th[o] = h;
      if (tl) tl[o] = __float2bfloat16(vv - __bfloat162float(h));
    }
  } else {
    size_t w = (size_t)(blk - 16384) * 256 + threadIdx.x;
    const int4* p = (const int4*)mask + w * 8;
    uint32_t vv = 0;
#pragma unroll
    for (int i = 0; i < 8; i++) {
      int4 m = p[i];
      vv |= (m.x != 0 ? 1u : 0u) << (i * 4);
      vv |= (m.y != 0 ? 1u : 0u) << (i * 4 + 1);
      vv |= (m.z != 0 ? 1u : 0u) << (i * 4 + 2);
      vv |= (m.w != 0 ? 1u : 0u) << (i * 4 + 3);
    }
    bits[w] = vv;
  }
}

// ---- Q/K projection (split hi/lo), grid.z selects ----
__global__ void __launch_bounds__(256, 2) mmQK() {
  extern __shared__ char sm[];
  const uint32_t sb = s2u(sm);
  const int z = blockIdx.z;
  const __nv_bfloat16* Ah = z ? g_kh : g_qh;
  const __nv_bfloat16* Al = z ? g_kl : g_ql;
  const __nv_bfloat16* Bh = z ? g_wkh : g_wqh;
  const __nv_bfloat16* Bl = z ? g_wkl : g_wql;
  __nv_bfloat16* DH = z ? g_Kh : g_Qh;
  __nv_bfloat16* DL = z ? g_Kl : g_Ql;
  const float sc = z ? 1.f : 0.125f;

  const int tid = threadIdx.x, lane = tid & 31, wid = tid >> 5;
  const int wy = wid >> 1, wx = wid & 1;
  const int m0 = blockIdx.y * 128, n0 = blockIdx.x * 128;
  const int lr = (lane & 7) + ((lane >> 3) & 1) * 8, lc = (lane >> 4) * 8;
  const int r0 = lane >> 2, c0 = 2 * (lane & 3);

  float acc[2][8][4];
#pragma unroll
  for (int i = 0; i < 2; i++)
#pragma unroll
    for (int j = 0; j < 8; j++)
#pragma unroll
      for (int t = 0; t < 4; t++) acc[i][j][t] = 0.f;

  auto issue = [&](int kc, int buf) {
    uint32_t bs = sb + buf * 40960;
#pragma unroll
    for (int i = 0; i < 2; i++) {
      int idx = tid + i * 256, row = idx >> 2, seg = idx & 3;
      uint32_t d0 = bs + row * 80 + seg * 16;
      size_t sa = (size_t)(m0 + row) * D + kc * 32 + seg * 8;
      size_t sg = (size_t)(n0 + row) * D + kc * 32 + seg * 8;
      CPA(d0, Ah + sa);
      CPA(d0 + 10240, Bh + sg);
      CPA(d0 + 20480, Al + sa);
      CPA(d0 + 30720, Bl + sg);
    }
    CPC();
  };

  issue(0, 0);
  for (int kc = 0; kc < 32; kc++) {
    if (kc < 31) { issue(kc + 1, (kc + 1) & 1); CPW(1); } else { CPW(0); }
    __syncthreads();
    uint32_t bs = sb + (kc & 1) * 40960;
#pragma unroll
    for (int ks = 0; ks < 2; ks++) {
      uint32_t aH[2][4], aL[2][4];
#pragma unroll
      for (int mi = 0; mi < 2; mi++) {
        uint32_t o = ((wy * 32 + mi * 16 + lr) * 40 + ks * 16 + lc) * 2;
        ldm4(aH[mi], bs + o);
        ldm4(aL[mi], bs + 20480 + o);
      }
#pragma unroll
      for (int h2 = 0; h2 < 2; h2++) {
        uint32_t bH[2][4], bL[2][4];
#pragma unroll
        for (int ni = 0; ni < 2; ni++) {
          uint32_t o = ((wx * 64 + (h2 * 2 + ni) * 16 + lr) * 40 + ks * 16 + lc) * 2;
          ldm4(bH[ni], bs + 10240 + o);
          ldm4(bL[ni], bs + 30720 + o);
        }
#pragma unroll
        for (int mi = 0; mi < 2; mi++)
#pragma unroll
          for (int nj2 = 0; nj2 < 4; nj2++) {
            int nj = h2 * 4 + nj2;
            uint32_t bb2[2] = {bH[nj2 >> 1][nj2 & 1], bH[nj2 >> 1][(nj2 & 1) + 2]};
            uint32_t bl2[2] = {bL[nj2 >> 1][nj2 & 1], bL[nj2 >> 1][(nj2 & 1) + 2]};
            mma_bf(acc[mi][nj], aH[mi], bb2);
            mma_bf(acc[mi][nj], aH[mi], bl2);
            mma_bf(acc[mi][nj], aL[mi], bb2);
          }
      }
    }
    __syncthreads();
  }

#pragma unroll
  for (int mi = 0; mi < 2; mi++)
#pragma unroll
    for (int nj = 0; nj < 8; nj++)
#pragma unroll
      for (int hf = 0; hf < 2; hf++) {
        int mrow = m0 + wy * 32 + mi * 16 + r0 + hf * 8;
        int ncol = n0 + wx * 64 + nj * 8 + c0;
        float v0 = acc[mi][nj][hf * 2] * sc, v1 = acc[mi][nj][hf * 2 + 1] * sc;
        __nv_bfloat16 h0 = __float2bfloat16(v0), h1 = __float2bfloat16(v1);
        int bb = mrow >> 11, ll = mrow & 2047, hh = ncol >> 6, dk = ncol & 63;
        size_t o = (((size_t)bb * H + hh) * L + ll) * 64 + dk;
        *(uint32_t*)(DH + o) = packbf(v0, v1);
        *(uint32_t*)(DL + o) = packbf(v0 - __bfloat162float(h0), v1 - __bfloat162float(h1));
      }
}

// ---- HMMA GEMM (single bf16): MODE 2=V(transpose out) 3=FC(residual) ----
template <int MODE>
__global__ void __launch_bounds__(256, 2) mmk(const __nv_bfloat16* __restrict__ Ah,
    const __nv_bfloat16* __restrict__ Bh, const float* __restrict__ resid) {
  extern __shared__ char sm[];
  const uint32_t sb = s2u(sm);
  const int tid = threadIdx.x, lane = tid & 31, wid = tid >> 5;
  const int wy = wid >> 1, wx = wid & 1;
  const int m0 = blockIdx.y * 128, n0 = blockIdx.x * 128;
  const int lr = (lane & 7) + ((lane >> 3) & 1) * 8, lc = (lane >> 4) * 8;
  const int r0 = lane >> 2, c0 = 2 * (lane & 3);

  float acc[2][8][4];
#pragma unroll
  for (int i = 0; i < 2; i++)
#pragma unroll
    for (int j = 0; j < 8; j++)
#pragma unroll
      for (int t = 0; t < 4; t++) acc[i][j][t] = 0.f;

  auto issue = [&](int kc, int buf) {
    uint32_t bs = sb + buf * 20480;
#pragma unroll
    for (int i = 0; i < 2; i++) {
      int idx = tid + i * 256, row = idx >> 2, seg = idx & 3;
      uint32_t d0 = bs + row * 80 + seg * 16;
      CPA(d0, Ah + (size_t)(m0 + row) * D + kc * 32 + seg * 8);
      CPA(d0 + 10240, Bh + (size_t)(n0 + row) * D + kc * 32 + seg * 8);
    }
    CPC();
  };

  issue(0, 0);
  for (int kc = 0; kc < 32; kc++) {
    if (kc < 31) { issue(kc + 1, (kc + 1) & 1); CPW(1); } else { CPW(0); }
    __syncthreads();
    uint32_t bs = sb + (kc & 1) * 20480;
#pragma unroll
    for (int ks = 0; ks < 2; ks++) {
      uint32_t aH[2][4], bH[4][4];
#pragma unroll
      for (int mi = 0; mi < 2; mi++)
        ldm4(aH[mi], bs + ((wy * 32 + mi * 16 + lr) * 40 + ks * 16 + lc) * 2);
#pragma unroll
      for (int ni = 0; ni < 4; ni++)
        ldm4(bH[ni], bs + 10240 + ((wx * 64 + ni * 16 + lr) * 40 + ks * 16 + lc) * 2);
#pragma unroll
      for (int mi = 0; mi < 2; mi++)
#pragma unroll
        for (int nj = 0; nj < 8; nj++) {
          uint32_t bb2[2] = {bH[nj >> 1][nj & 1], bH[nj >> 1][(nj & 1) + 2]};
          mma_bf(acc[mi][nj], aH[mi], bb2);
        }
    }
    __syncthreads();
  }

  if (MODE == 3) {
#pragma unroll
    for (int mi = 0; mi < 2; mi++)
#pragma unroll
      for (int nj = 0; nj < 8; nj++)
#pragma unroll
        for (int hf = 0; hf < 2; hf++) {
          int mrow = m0 + wy * 32 + mi * 16 + r0 + hf * 8;
          int ncol = n0 + wx * 64 + nj * 8 + c0;
          size_t o = (size_t)mrow * D + ncol;
          float2 rv = *(const float2*)(resid + o);
          *(float2*)(g_X + o) = make_float2(acc[mi][nj][hf * 2] + rv.x,
                                            acc[mi][nj][hf * 2 + 1] + rv.y);
        }
  } else {
    __nv_bfloat16* Cs = (__nv_bfloat16*)sm;
#pragma unroll
    for (int mi = 0; mi < 2; mi++)
#pragma unroll
      for (int nj = 0; nj < 8; nj++)
#pragma unroll
        for (int hf = 0; hf < 2; hf++) {
          int rl = wy * 32 + mi * 16 + r0 + hf * 8;
          int cl = wx * 64 + nj * 8 + c0;
          *(uint32_t*)(Cs + rl * 132 + cl) =
              packbf(acc[mi][nj][hf * 2], acc[mi][nj][hf * 2 + 1]);
        }
    __syncthreads();
    int bb = m0 >> 11, l0g = m0 & 2047;
#pragma unroll
    for (int rep = 0; rep < 8; rep++) {
      int col = rep * 16 + (tid >> 4);
      int ls = (tid & 15) * 8;
      int ncol = n0 + col, hh = ncol >> 6, dv = ncol & 63;
      union { unsigned short s[8]; uint4 u; } tmp;
#pragma unroll
      for (int j = 0; j < 8; j++) tmp.s[j] = ((unsigned short*)Cs)[(ls + j) * 132 + col];
      *(uint4*)(g_Vt + (((size_t)bb * H + hh) * 64 + dv) * L + l0g + ls) = tmp.u;
    }
  }
}

// ---- fused attention: 512 threads; TRIPLE buffer, 1 sync/chunk ----
// smem: KH[3] @ 0/18432/36864; KL[3] @ 55296/73728/92160;
//       VT[3] @ 110592/128000/145408; RED @162816(34816); QL @197632(18432);
//       PS @216064(1024); SI @217088(512). Total 217600 <= 227KB cap.
__device__ __constant__ int c_oKH[3] = {0, 18432, 36864};
__device__ __constant__ int c_oKL[3] = {55296, 73728, 92160};
__device__ __constant__ int c_oVT[3] = {110592, 128000, 145408};
constexpr int oRED = 162816;
constexpr int oQL = 197632;
constexpr int oPS = 216064, oSI = 217088;
constexpr int ATTN_SMEM = 217600;

__global__ void __launch_bounds__(512) attn_tc(float* __restrict__ attnE) {
  extern __shared__ char sm[];
  const uint32_t sb = s2u(sm);
  const int tid = threadIdx.x, lane = tid & 31, wid = tid >> 5;
  const int wm = wid >> 1, wx = wid & 1;
  const int b = blockIdx.z, h = blockIdx.y, q0 = blockIdx.x * 128, bh = b * H + h;
  const int lr = (lane & 7) + ((lane >> 3) & 1) * 8, lc = (lane >> 4) * 8;
  const int r0 = lane >> 2, c0 = 2 * (lane & 3);

  {  // stage Q: hi into RED area (row stride 144B), lo into QL
    const __nv_bfloat16* Qh = g_Qh + ((size_t)bh * L + q0) * 64;
    const __nv_bfloat16* Ql = g_Ql + ((size_t)bh * L + q0) * 64;
#pragma unroll
    for (int i = 0; i < 2; i++) {
      int idx = tid + i * 512, row = idx >> 3, seg = idx & 7;
      *(uint4*)(sm + oRED + row * 144 + seg * 16) = *(const uint4*)(Qh + (size_t)row * 64 + seg * 8);
      *(uint4*)(sm + oQL + row * 144 + seg * 16) = *(const uint4*)(Ql + (size_t)row * 64 + seg * 8);
    }
  }
  __syncthreads();

  auto issue = [&](int kc, int buf) {
    uint32_t oK = sb + c_oKH[buf];
    uint32_t oKl = sb + c_oKL[buf];
    uint32_t oV = sb + c_oVT[buf];
    const __nv_bfloat16* Kh = g_Kh + ((size_t)bh * L + kc * 128) * 64;
    const __nv_bfloat16* Kl = g_Kl + ((size_t)bh * L + kc * 128) * 64;
    const __nv_bfloat16* Vt = g_Vt + (size_t)bh * 64 * L + kc * 128;
#pragma unroll
    for (int i = 0; i < 2; i++) {
      int idx = tid + i * 512, row = idx >> 3, seg = idx & 7;
      CPA(oK + row * 144 + seg * 16, Kh + (size_t)row * 64 + seg * 8);
      CPA(oKl + row * 144 + seg * 16, Kl + (size_t)row * 64 + seg * 8);
    }
#pragma unroll
    for (int i = 0; i < 2; i++) {
      int idx = tid + i * 512, row = idx >> 4, seg = idx & 15;
      CPA(oV + row * 272 + seg * 16, Vt + (size_t)row * L + seg * 8);
    }
    CPC();
  };
  issue(0, 0);
  issue(1, 1);

  uint32_t qh[4][4];
#pragma unroll
  for (int ks = 0; ks < 4; ks++)
    ldm4(qh[ks], sb + oRED + ((wm * 16 + lr) * 72 + ks * 16 + lc) * 2);

  float acc_o[8][4];
#pragma unroll
  for (int j = 0; j < 8; j++)
#pragma unroll
    for (int t = 0; t < 4; t++) acc_o[j][t] = 0.f;
  float rs[2] = {0.f, 0.f};

  for (int kc = 0; kc < 16; kc++) {
    // single sync: all warps done with chunk kc-1 (whose reads used buffer
    // (kc-1)%3 == (kc+2)%3 — the buffer issue() overwrites below)
    __syncthreads();
    if (kc < 14) { issue(kc + 2, (kc + 2) % 3); CPW(2); }
    else if (kc == 14) { CPW(1); }
    else { CPW(0); }
    const int bf = kc % 3;
    uint32_t bK = sb + c_oKH[bf];
    uint32_t bKl = sb + c_oKL[bf];
    uint32_t bV = sb + c_oVT[bf];

    // S: ks-outer, full nj width — 8 independent accumulator chains
    float sacc[8][4];
#pragma unroll
    for (int j = 0; j < 8; j++)
#pragma unroll
      for (int t = 0; t < 4; t++) sacc[j][t] = 0.f;

#pragma unroll
    for (int ks = 0; ks < 4; ks++) {
      uint32_t ql4[4], bh4[4][4], bl4[4][4];
      ldm4(ql4, sb + oQL + ((wm * 16 + lr) * 72 + ks * 16 + lc) * 2);
#pragma unroll
      for (int ni = 0; ni < 4; ni++) {
        uint32_t o = ((wx * 64 + ni * 16 + lr) * 72 + ks * 16 + lc) * 2;
        ldm4(bh4[ni], bK + o);
        ldm4(bl4[ni], bKl + o);
      }
#pragma unroll
      for (int nj = 0; nj < 8; nj++) {
        uint32_t bb2[2] = {bh4[nj >> 1][nj & 1], bh4[nj >> 1][(nj & 1) + 2]};
        uint32_t bl2[2] = {bl4[nj >> 1][nj & 1], bl4[nj >> 1][(nj & 1) + 2]};
        mma_bf(sacc[nj], qh[ks], bb2);
        mma_bf(sacc[nj], qh[ks], bl2);
        mma_bf(sacc[nj], ql4, bb2);
      }
    }

    // epilogue: mask (fast path), exp, fp32->gmem, rowsum, pack
    uint32_t eab[8][2];
    uint32_t wmA[2], wmB[2];
#pragma unroll
    for (int hf = 0; hf < 2; hf++) {
      int qr = q0 + wm * 16 + r0 + hf * 8;
      size_t mo = ((size_t)b * L + qr) * 64 + kc * 4 + wx * 2;
      wmA[hf] = g_mbits[mo];
      wmB[hf] = g_mbits[mo + 1];
    }
#pragma unroll
    for (int nj = 0; nj < 8; nj++)
#pragma unroll
      for (int hf = 0; hf < 2; hf++) {
        int qr = q0 + wm * 16 + r0 + hf * 8;
        int colL = wx * 64 + nj * 8 + c0;
        uint32_t w = (nj < 4) ? wmA[hf] : wmB[hf];
        float e0, e1;
        if (w == 0xFFFFFFFFu) {
          e0 = __expf(fminf(sacc[nj][hf * 2], 60.f));
          e1 = __expf(fminf(sacc[nj][hf * 2 + 1], 60.f));
        } else {
          int bp = (nj & 3) * 8 + c0;
          e0 = ((w >> bp) & 1u) ? __expf(fminf(sacc[nj][hf * 2], 60.f)) : 0.f;
          e1 = ((w >> (bp + 1)) & 1u) ? __expf(fminf(sacc[nj][hf * 2 + 1], 60.f)) : 0.f;
        }
        rs[hf] += e0 + e1;
        *(float2*)(attnE + ((size_t)bh * L + qr) * L + kc * 128 + colL) = make_float2(e0, e1);
        eab[nj][hf] = packbf(e0, e1);
      }

    // O += E @ Vt
#pragma unroll
    for (int kt = 0; kt < 4; kt++) {
      uint32_t vb[4][4];
#pragma unroll
      for (int ni = 0; ni < 4; ni++)
        ldm4(vb[ni], bV + ((ni * 16 + lr) * 136 + wx * 64 + kt * 16 + lc) * 2);
      uint32_t ae[4] = {eab[2 * kt][0], eab[2 * kt][1],
                        eab[2 * kt + 1][0], eab[2 * kt + 1][1]};
#pragma unroll
      for (int njO = 0; njO < 8; njO++) {
        uint32_t bb2[2] = {vb[njO >> 1][njO & 1], vb[njO >> 1][(njO & 1) + 2]};
        mma_bf(acc_o[njO], ae, bb2);
      }
    }
  }

  // rowsum reduce -> sinv
  float* ps = (float*)(sm + oPS);
  float* sinv = (float*)(sm + oSI);
#pragma unroll
  for (int j = 0; j < 2; j++) {
    float v = rs[j];
    v += __shfl_xor_sync(0xffffffffu, v, 1);
    v += __shfl_xor_sync(0xffffffffu, v, 2);
    if ((lane & 3) == 0) ps[wx * 128 + wm * 16 + j * 8 + r0] = v;
  }
  __syncthreads();
  if (tid < 128) {
    float t = ps[tid] + ps[128 + tid];
    sinv[tid] = (t > 0.f) ? 1.f / t : 0.f;
  }
  __syncthreads();

  // cross-wx O reduction via RED, then normalized store
  float* red = (float*)(sm + oRED);
  if (wx == 1) {
#pragma unroll
    for (int hf = 0; hf < 2; hf++) {
      int rl = wm * 16 + r0 + hf * 8;
#pragma unroll
      for (int njO = 0; njO < 8; njO++)
        *(float2*)&red[rl * 68 + njO * 8 + c0] =
            make_float2(acc_o[njO][hf * 2], acc_o[njO][hf * 2 + 1]);
    }
  }
  __syncthreads();
  if (wx == 0) {
#pragma unroll
    for (int hf = 0; hf < 2; hf++) {
      int rl = wm * 16 + r0 + hf * 8;
      float iv = sinv[rl];
      int qr = q0 + rl;
#pragma unroll
      for (int njO = 0; njO < 8; njO++) {
        float2 p = *(float2*)&red[rl * 68 + njO * 8 + c0];
        *(uint32_t*)(g_Obf + ((size_t)b * L + qr) * 1024 + h * 64 + njO * 8 + c0) =
            packbf((acc_o[njO][hf * 2] + p.x) * iv,
                   (acc_o[njO][hf * 2 + 1] + p.y) * iv);
      }
    }
  }

  // fold attn normalization (re-read + scale)
  int rr = tid >> 2, sg = tid & 3;
  float iv2 = sinv[rr];
  float4* np = (float4*)(attnE + ((size_t)bh * L + q0 + rr) * L + sg * 512);
#pragma unroll 4
  for (int i = 0; i < 128; i++) {
    float4 v = np[i];
    v.x *= iv2; v.y *= iv2; v.z *= iv2; v.w *= iv2;
    np[i] = v;
  }
}

// ---- LayerNorm ----
__global__ void __launch_bounds__(256) ln_kernel(const float* __restrict__ gamma,
    const float* __restrict__ beta, float* __restrict__ out) {
  const int row = blockIdx.x, tid = threadIdx.x;
  const float* x = g_X + (size_t)row * D;
  float4 v = *(const float4*)&x[tid * 4];
  float s = v.x + v.y + v.z + v.w;
  float s2 = v.x * v.x + v.y * v.y + v.z * v.z + v.w * v.w;
#pragma unroll
  for (int off = 16; off; off >>= 1) {
    s += __shfl_xor_sync(0xffffffffu, s, off);
    s2 += __shfl_xor_sync(0xffffffffu, s2, off);
  }
  __shared__ float ws[8], ws2[8], mean_s, rstd_s;
  int w = tid >> 5, lid = tid & 31;
  if (lid == 0) { ws[w] = s; ws2[w] = s2; }
  __syncthreads();
  if (tid == 0) {
    float S = 0.f, S2 = 0.f;
#pragma unroll
    for (int i = 0; i < 8; i++) { S += ws[i]; S2 += ws2[i]; }
    float mu = S * (1.f / D);
    mean_s = mu;
    rstd_s = rsqrtf(S2 * (1.f / D) - mu * mu + 1e-6f);
  }
  __syncthreads();
  float mu = mean_s, rstd = rstd_s;
  float4 g4 = *(const float4*)&gamma[tid * 4];
  float4 b4 = *(const float4*)&beta[tid * 4];
  *(float4*)&out[(size_t)row * D + tid * 4] = make_float4(
      (v.x - mu) * rstd * g4.x + b4.x, (v.y - mu) * rstd * g4.y + b4.y,
      (v.z - mu) * rstd * g4.z + b4.z, (v.w - mu) * rstd * g4.w + b4.w);
}

extern "C" void kernel_launch(void* const* d_in, const int* in_sizes, int n_in,
                              void* d_out, int out_size) {
  const float* q = (const float*)d_in[0];
  const float* k = (const float*)d_in[1];
  const float* v = (const float*)d_in[2];
  const int* mask = (const int*)d_in[3];
  const float* wq = (const float*)d_in[4];
  const float* wk = (const float*)d_in[5];
  const float* wv = (const float*)d_in[6];
  const float* wfc = (const float*)d_in[7];
  const float* lng = (const float*)d_in[8];
  const float* lnb = (const float*)d_in[9];
  (void)in_sizes; (void)n_in; (void)out_size;
  float* out = (float*)d_out;
  float* attn = out + OUT_ELEMS;

  __nv_bfloat16 *p_vbf, *p_wvh, *p_wfh, *p_obf;
  uint32_t* p_mb;
  cudaGetSymbolAddress((void**)&p_vbf, g_vbf);
  cudaGetSymbolAddress((void**)&p_wvh, g_wvh);
  cudaGetSymbolAddress((void**)&p_wfh, g_wfh);
  cudaGetSymbolAddress((void**)&p_obf, g_Obf);
  cudaGetSymbolAddress((void**)&p_mb, g_mbits);

  cudaFuncSetAttribute(mmQK, cudaFuncAttributeMaxDynamicSharedMemorySize, 81920);
  cudaFuncSetAttribute(mmk<2>, cudaFuncAttributeMaxDynamicSharedMemorySize, 40960);
  cudaFuncSetAttribute(mmk<3>, cudaFuncAttributeMaxDynamicSharedMemorySize, 40960);
  cudaFuncSetAttribute(attn_tc, cudaFuncAttributeMaxDynamicSharedMemorySize, ATTN_SMEM);

  // launch order: attn_tc at index 3 (the observed ncu capture slot)
  prep<<<17408, 256>>>(q, k, v, wq, wk, wv, wfc, mask, p_mb);             // 0
  mmQK<<<dim3(8, 32, 2), 256, 81920>>>();                                 // 1
  mmk<2><<<dim3(8, 32), 256, 40960>>>(p_vbf, p_wvh, nullptr);             // 2
  attn_tc<<<dim3(L / 128, H, B), 512, ATTN_SMEM>>>(attn);                 // 3
  mmk<3><<<dim3(8, 32), 256, 40960>>>(p_obf, p_wfh, q);                   // 4
  ln_kernel<<<M, 256>>>(lng, lnb, out);                                   // 5
}

// round 15
// speedup vs baseline: 1.2941x; 1.2941x over previous
#include <cuda_runtime.h>
#include <cuda_bf16.h>
#include <cstdint>

constexpr int B = 2, L = 2048, D = 1024, H = 16;
constexpr int M = B * L;
constexpr int OUT_ELEMS = B * L * D;

// ---- static device scratch ----
__device__ __align__(16) __nv_bfloat16 g_qh[M * D], g_ql[M * D];
__device__ __align__(16) __nv_bfloat16 g_kh[M * D], g_kl[M * D], g_vbf[M * D];
__device__ __align__(16) __nv_bfloat16 g_wqh[D * D], g_wql[D * D];
__device__ __align__(16) __nv_bfloat16 g_wkh[D * D], g_wkl[D * D];
__device__ __align__(16) __nv_bfloat16 g_wvh[D * D], g_wfh[D * D];
__device__ __align__(16) __nv_bfloat16 g_Qh[M * D], g_Ql[M * D];
__device__ __align__(16) __nv_bfloat16 g_Kh[M * D], g_Kl[M * D];
__device__ __align__(16) __nv_bfloat16 g_Vt[M * D];   // (b,h,dv,l)
__device__ __align__(16) __nv_bfloat16 g_Obf[M * D];  // (b,l,h*dv)
__device__ __align__(16) float g_X[M * D];
__device__ uint32_t g_mbits[(size_t)B * L * (L / 32)];

// ---- helpers ----
__device__ __forceinline__ uint32_t s2u(const void* p) {
  uint32_t a;
  asm("{ .reg .u64 t; cvta.to.shared.u64 t, %1; cvt.u32.u64 %0, t; }" : "=r"(a) : "l"(p));
  return a;
}
#define CPA(dst, src) asm volatile("cp.async.cg.shared.global [%0], [%1], 16;" :: "r"(dst), "l"(src))
#define CPC() asm volatile("cp.async.commit_group;" ::: "memory")
#define CPW(n) asm volatile("cp.async.wait_group %0;" :: "n"(n) : "memory")
__device__ __forceinline__ void ldm4(uint32_t* r, uint32_t a) {
  asm volatile("ldmatrix.sync.aligned.m8n8.x4.shared.b16 {%0,%1,%2,%3}, [%4];"
               : "=r"(r[0]), "=r"(r[1]), "=r"(r[2]), "=r"(r[3]) : "r"(a));
}
__device__ __forceinline__ void mma_bf(float* d, const uint32_t* a, const uint32_t* b) {
  asm volatile(
      "mma.sync.aligned.m16n8k16.row.col.f32.bf16.bf16.f32 "
      "{%0,%1,%2,%3},{%4,%5,%6,%7},{%8,%9},{%0,%1,%2,%3};"
      : "+f"(d[0]), "+f"(d[1]), "+f"(d[2]), "+f"(d[3])
      : "r"(a[0]), "r"(a[1]), "r"(a[2]), "r"(a[3]), "r"(b[0]), "r"(b[1]));
}
__device__ __forceinline__ uint32_t packbf(float a, float b) {
  __nv_bfloat162 p = __halves2bfloat162(__float2bfloat16(a), __float2bfloat16(b));
  return *(uint32_t*)&p;
}

// ---- merged prep kernel ----
__global__ void __launch_bounds__(256) prep(const float* __restrict__ q,
                                            const float* __restrict__ k,
                                            const float* __restrict__ v,
                                            const float* __restrict__ wq,
                                            const float* __restrict__ wk,
                                            const float* __restrict__ wv,
                                            const float* __restrict__ wfc,
                                            const int* __restrict__ mask,
                                            uint32_t* __restrict__ bits) {
  const int blk = blockIdx.x;
  if (blk < 12288) {
    const int z = blk >> 12;
    const int lb = blk & 4095;
    size_t i = (size_t)lb * 1024 + threadIdx.x * 4;
    const float* in = (z == 0) ? q : (z == 1) ? k : v;
    float4 vv = *(const float4*)(in + i);
    if (z == 2) {
      *(uint2*)(g_vbf + i) = make_uint2(packbf(vv.x, vv.y), packbf(vv.z, vv.w));
      return;
    }
    __nv_bfloat16* hi = (z == 0) ? g_qh : g_kh;
    __nv_bfloat16* lo = (z == 0) ? g_ql : g_kl;
    float a[4] = {vv.x, vv.y, vv.z, vv.w};
    uint32_t ph[2], pl[2];
#pragma unroll
    for (int j = 0; j < 2; j++) {
      float x0 = a[j * 2], x1 = a[j * 2 + 1];
      __nv_bfloat16 h0 = __float2bfloat16(x0), h1 = __float2bfloat16(x1);
      ph[j] = packbf(x0, x1);
      pl[j] = packbf(x0 - __bfloat162float(h0), x1 - __bfloat162float(h1));
    }
    *(uint2*)(hi + i) = make_uint2(ph[0], ph[1]);
    *(uint2*)(lo + i) = make_uint2(pl[0], pl[1]);
  } else if (blk < 16384) {
    const int bw = blk - 12288;
    const int z = bw >> 10;
    const int lb = bw & 1023;
    const float* w = (z == 0) ? wq : (z == 1) ? wk : (z == 2) ? wv : wfc;
    __nv_bfloat16* th = (z == 0) ? g_wqh : (z == 1) ? g_wkh : (z == 2) ? g_wvh : g_wfh;
    __nv_bfloat16* tl = (z == 0) ? g_wql : (z == 1) ? g_wkl : nullptr;
    __shared__ float t[32][33];
    int tx = threadIdx.x & 31, ty = threadIdx.x >> 5;
    int x0 = (lb & 31) * 32, y0 = (lb >> 5) * 32;
#pragma unroll
    for (int i = 0; i < 4; i++)
      t[ty + i * 8][tx] = w[(size_t)(y0 + ty + i * 8) * D + x0 + tx];
    __syncthreads();
#pragma unroll
    for (int i = 0; i < 4; i++) {
      float vv = t[tx][ty + i * 8];
      __nv_bfloat16 h = __float2bfloat16(vv);
      size_t o = (size_t)(x0 + ty + i * 8) * D + y0 + tx;
      th[o] = h;
      if (tl) tl[o] = __float2bfloat16(vv - __bfloat162float(h));
    }
  } else {
    size_t w = (size_t)(blk - 16384) * 256 + threadIdx.x;
    const int4* p = (const int4*)mask + w * 8;
    uint32_t vv = 0;
#pragma unroll
    for (int i = 0; i < 8; i++) {
      int4 m = p[i];
      vv |= (m.x != 0 ? 1u : 0u) << (i * 4);
      vv |= (m.y != 0 ? 1u : 0u) << (i * 4 + 1);
      vv |= (m.z != 0 ? 1u : 0u) << (i * 4 + 2);
      vv |= (m.w != 0 ? 1u : 0u) << (i * 4 + 3);
    }
    bits[w] = vv;
  }
}

// ---- Q/K projection (split hi/lo), grid.z selects ----
__global__ void __launch_bounds__(256, 2) mmQK() {
  extern __shared__ char sm[];
  const uint32_t sb = s2u(sm);
  const int z = blockIdx.z;
  const __nv_bfloat16* Ah = z ? g_kh : g_qh;
  const __nv_bfloat16* Al = z ? g_kl : g_ql;
  const __nv_bfloat16* Bh = z ? g_wkh : g_wqh;
  const __nv_bfloat16* Bl = z ? g_wkl : g_wql;
  __nv_bfloat16* DH = z ? g_Kh : g_Qh;
  __nv_bfloat16* DL = z ? g_Kl : g_Ql;
  const float sc = z ? 1.f : 0.125f;

  const int tid = threadIdx.x, lane = tid & 31, wid = tid >> 5;
  const int wy = wid >> 1, wx = wid & 1;
  const int m0 = blockIdx.y * 128, n0 = blockIdx.x * 128;
  const int lr = (lane & 7) + ((lane >> 3) & 1) * 8, lc = (lane >> 4) * 8;
  const int r0 = lane >> 2, c0 = 2 * (lane & 3);

  float acc[2][8][4];
#pragma unroll
  for (int i = 0; i < 2; i++)
#pragma unroll
    for (int j = 0; j < 8; j++)
#pragma unroll
      for (int t = 0; t < 4; t++) acc[i][j][t] = 0.f;

  auto issue = [&](int kc, int buf) {
    uint32_t bs = sb + buf * 40960;
#pragma unroll
    for (int i = 0; i < 2; i++) {
      int idx = tid + i * 256, row = idx >> 2, seg = idx & 3;
      uint32_t d0 = bs + row * 80 + seg * 16;
      size_t sa = (size_t)(m0 + row) * D + kc * 32 + seg * 8;
      size_t sg = (size_t)(n0 + row) * D + kc * 32 + seg * 8;
      CPA(d0, Ah + sa);
      CPA(d0 + 10240, Bh + sg);
      CPA(d0 + 20480, Al + sa);
      CPA(d0 + 30720, Bl + sg);
    }
    CPC();
  };

  issue(0, 0);
  for (int kc = 0; kc < 32; kc++) {
    if (kc < 31) { issue(kc + 1, (kc + 1) & 1); CPW(1); } else { CPW(0); }
    __syncthreads();
    uint32_t bs = sb + (kc & 1) * 40960;
#pragma unroll
    for (int ks = 0; ks < 2; ks++) {
      uint32_t aH[2][4], aL[2][4];
#pragma unroll
      for (int mi = 0; mi < 2; mi++) {
        uint32_t o = ((wy * 32 + mi * 16 + lr) * 40 + ks * 16 + lc) * 2;
        ldm4(aH[mi], bs + o);
        ldm4(aL[mi], bs + 20480 + o);
      }
#pragma unroll
      for (int h2 = 0; h2 < 2; h2++) {
        uint32_t bH[2][4], bL[2][4];
#pragma unroll
        for (int ni = 0; ni < 2; ni++) {
          uint32_t o = ((wx * 64 + (h2 * 2 + ni) * 16 + lr) * 40 + ks * 16 + lc) * 2;
          ldm4(bH[ni], bs + 10240 + o);
          ldm4(bL[ni], bs + 30720 + o);
        }
#pragma unroll
        for (int mi = 0; mi < 2; mi++)
#pragma unroll
          for (int nj2 = 0; nj2 < 4; nj2++) {
            int nj = h2 * 4 + nj2;
            uint32_t bb2[2] = {bH[nj2 >> 1][nj2 & 1], bH[nj2 >> 1][(nj2 & 1) + 2]};
            uint32_t bl2[2] = {bL[nj2 >> 1][nj2 & 1], bL[nj2 >> 1][(nj2 & 1) + 2]};
            mma_bf(acc[mi][nj], aH[mi], bb2);
            mma_bf(acc[mi][nj], aH[mi], bl2);
            mma_bf(acc[mi][nj], aL[mi], bb2);
          }
      }
    }
    __syncthreads();
  }

#pragma unroll
  for (int mi = 0; mi < 2; mi++)
#pragma unroll
    for (int nj = 0; nj < 8; nj++)
#pragma unroll
      for (int hf = 0; hf < 2; hf++) {
        int mrow = m0 + wy * 32 + mi * 16 + r0 + hf * 8;
        int ncol = n0 + wx * 64 + nj * 8 + c0;
        float v0 = acc[mi][nj][hf * 2] * sc, v1 = acc[mi][nj][hf * 2 + 1] * sc;
        __nv_bfloat16 h0 = __float2bfloat16(v0), h1 = __float2bfloat16(v1);
        int bb = mrow >> 11, ll = mrow & 2047, hh = ncol >> 6, dk = ncol & 63;
        size_t o = (((size_t)bb * H + hh) * L + ll) * 64 + dk;
        *(uint32_t*)(DH + o) = packbf(v0, v1);
        *(uint32_t*)(DL + o) = packbf(v0 - __bfloat162float(h0), v1 - __bfloat162float(h1));
      }
}

// ---- HMMA GEMM (single bf16): MODE 2=V(transpose out) 3=FC(residual) ----
template <int MODE>
__global__ void __launch_bounds__(256, 2) mmk(const __nv_bfloat16* __restrict__ Ah,
    const __nv_bfloat16* __restrict__ Bh, const float* __restrict__ resid) {
  extern __shared__ char sm[];
  const uint32_t sb = s2u(sm);
  const int tid = threadIdx.x, lane = tid & 31, wid = tid >> 5;
  const int wy = wid >> 1, wx = wid & 1;
  const int m0 = blockIdx.y * 128, n0 = blockIdx.x * 128;
  const int lr = (lane & 7) + ((lane >> 3) & 1) * 8, lc = (lane >> 4) * 8;
  const int r0 = lane >> 2, c0 = 2 * (lane & 3);

  float acc[2][8][4];
#pragma unroll
  for (int i = 0; i < 2; i++)
#pragma unroll
    for (int j = 0; j < 8; j++)
#pragma unroll
      for (int t = 0; t < 4; t++) acc[i][j][t] = 0.f;

  auto issue = [&](int kc, int buf) {
    uint32_t bs = sb + buf * 20480;
#pragma unroll
    for (int i = 0; i < 2; i++) {
      int idx = tid + i * 256, row = idx >> 2, seg = idx & 3;
      uint32_t d0 = bs + row * 80 + seg * 16;
      CPA(d0, Ah + (size_t)(m0 + row) * D + kc * 32 + seg * 8);
      CPA(d0 + 10240, Bh + (size_t)(n0 + row) * D + kc * 32 + seg * 8);
    }
    CPC();
  };

  issue(0, 0);
  for (int kc = 0; kc < 32; kc++) {
    if (kc < 31) { issue(kc + 1, (kc + 1) & 1); CPW(1); } else { CPW(0); }
    __syncthreads();
    uint32_t bs = sb + (kc & 1) * 20480;
#pragma unroll
    for (int ks = 0; ks < 2; ks++) {
      uint32_t aH[2][4], bH[4][4];
#pragma unroll
      for (int mi = 0; mi < 2; mi++)
        ldm4(aH[mi], bs + ((wy * 32 + mi * 16 + lr) * 40 + ks * 16 + lc) * 2);
#pragma unroll
      for (int ni = 0; ni < 4; ni++)
        ldm4(bH[ni], bs + 10240 + ((wx * 64 + ni * 16 + lr) * 40 + ks * 16 + lc) * 2);
#pragma unroll
      for (int mi = 0; mi < 2; mi++)
#pragma unroll
        for (int nj = 0; nj < 8; nj++) {
          uint32_t bb2[2] = {bH[nj >> 1][nj & 1], bH[nj >> 1][(nj & 1) + 2]};
          mma_bf(acc[mi][nj], aH[mi], bb2);
        }
    }
    __syncthreads();
  }

  if (MODE == 3) {
#pragma unroll
    for (int mi = 0; mi < 2; mi++)
#pragma unroll
      for (int nj = 0; nj < 8; nj++)
#pragma unroll
        for (int hf = 0; hf < 2; hf++) {
          int mrow = m0 + wy * 32 + mi * 16 + r0 + hf * 8;
          int ncol = n0 + wx * 64 + nj * 8 + c0;
          size_t o = (size_t)mrow * D + ncol;
          float2 rv = *(const float2*)(resid + o);
          *(float2*)(g_X + o) = make_float2(acc[mi][nj][hf * 2] + rv.x,
                                            acc[mi][nj][hf * 2 + 1] + rv.y);
        }
  } else {
    __nv_bfloat16* Cs = (__nv_bfloat16*)sm;
#pragma unroll
    for (int mi = 0; mi < 2; mi++)
#pragma unroll
      for (int nj = 0; nj < 8; nj++)
#pragma unroll
        for (int hf = 0; hf < 2; hf++) {
          int rl = wy * 32 + mi * 16 + r0 + hf * 8;
          int cl = wx * 64 + nj * 8 + c0;
          *(uint32_t*)(Cs + rl * 132 + cl) =
              packbf(acc[mi][nj][hf * 2], acc[mi][nj][hf * 2 + 1]);
        }
    __syncthreads();
    int bb = m0 >> 11, l0g = m0 & 2047;
#pragma unroll
    for (int rep = 0; rep < 8; rep++) {
      int col = rep * 16 + (tid >> 4);
      int ls = (tid & 15) * 8;
      int ncol = n0 + col, hh = ncol >> 6, dv = ncol & 63;
      union { unsigned short s[8]; uint4 u; } tmp;
#pragma unroll
      for (int j = 0; j < 8; j++) tmp.s[j] = ((unsigned short*)Cs)[(ls + j) * 132 + col];
      *(uint4*)(g_Vt + (((size_t)bb * H + hh) * 64 + dv) * L + l0g + ls) = tmp.u;
    }
  }
}

// ---- fused attention: 512 threads; R13 double-buffer body; coalesced tail ----
constexpr int oKH0 = 0, oKL0 = 18432, oVT0 = 36864;
constexpr int oKH1 = 54272, oKL1 = 72704, oVT1 = 91136;
constexpr int oRED = 108544;
constexpr int oQL = 143360;
constexpr int oPS = 161792, oSI = 162816;
constexpr int ATTN_SMEM = 163328;

__global__ void __launch_bounds__(512) attn_tc(float* __restrict__ attnE) {
  extern __shared__ char sm[];
  const uint32_t sb = s2u(sm);
  const int tid = threadIdx.x, lane = tid & 31, wid = tid >> 5;
  const int wm = wid >> 1, wx = wid & 1;
  const int b = blockIdx.z, h = blockIdx.y, q0 = blockIdx.x * 128, bh = b * H + h;
  const int lr = (lane & 7) + ((lane >> 3) & 1) * 8, lc = (lane >> 4) * 8;
  const int r0 = lane >> 2, c0 = 2 * (lane & 3);

  {  // stage Q: hi into RED area (row stride 144B), lo into QL
    const __nv_bfloat16* Qh = g_Qh + ((size_t)bh * L + q0) * 64;
    const __nv_bfloat16* Ql = g_Ql + ((size_t)bh * L + q0) * 64;
#pragma unroll
    for (int i = 0; i < 2; i++) {
      int idx = tid + i * 512, row = idx >> 3, seg = idx & 7;
      *(uint4*)(sm + oRED + row * 144 + seg * 16) = *(const uint4*)(Qh + (size_t)row * 64 + seg * 8);
      *(uint4*)(sm + oQL + row * 144 + seg * 16) = *(const uint4*)(Ql + (size_t)row * 64 + seg * 8);
    }
  }
  __syncthreads();

  auto issue = [&](int kc, int buf) {
    uint32_t oK = sb + (buf ? oKH1 : oKH0);
    uint32_t oKl = sb + (buf ? oKL1 : oKL0);
    uint32_t oV = sb + (buf ? oVT1 : oVT0);
    const __nv_bfloat16* Kh = g_Kh + ((size_t)bh * L + kc * 128) * 64;
    const __nv_bfloat16* Kl = g_Kl + ((size_t)bh * L + kc * 128) * 64;
    const __nv_bfloat16* Vt = g_Vt + (size_t)bh * 64 * L + kc * 128;
#pragma unroll
    for (int i = 0; i < 2; i++) {
      int idx = tid + i * 512, row = idx >> 3, seg = idx & 7;
      CPA(oK + row * 144 + seg * 16, Kh + (size_t)row * 64 + seg * 8);
      CPA(oKl + row * 144 + seg * 16, Kl + (size_t)row * 64 + seg * 8);
    }
#pragma unroll
    for (int i = 0; i < 2; i++) {
      int idx = tid + i * 512, row = idx >> 4, seg = idx & 15;
      CPA(oV + row * 272 + seg * 16, Vt + (size_t)row * L + seg * 8);
    }
    CPC();
  };
  issue(0, 0);

  uint32_t qh[4][4];
#pragma unroll
  for (int ks = 0; ks < 4; ks++)
    ldm4(qh[ks], sb + oRED + ((wm * 16 + lr) * 72 + ks * 16 + lc) * 2);

  float acc_o[8][4];
#pragma unroll
  for (int j = 0; j < 8; j++)
#pragma unroll
    for (int t = 0; t < 4; t++) acc_o[j][t] = 0.f;
  float rs[2] = {0.f, 0.f};

  for (int kc = 0; kc < 16; kc++) {
    if (kc < 15) { issue(kc + 1, (kc + 1) & 1); CPW(1); } else { CPW(0); }
    __syncthreads();
    uint32_t bK = sb + ((kc & 1) ? oKH1 : oKH0);
    uint32_t bKl = sb + ((kc & 1) ? oKL1 : oKL0);
    uint32_t bV = sb + ((kc & 1) ? oVT1 : oVT0);

    // S: ks-outer, full nj width — 8 independent accumulator chains
    float sacc[8][4];
#pragma unroll
    for (int j = 0; j < 8; j++)
#pragma unroll
      for (int t = 0; t < 4; t++) sacc[j][t] = 0.f;

#pragma unroll
    for (int ks = 0; ks < 4; ks++) {
      uint32_t ql4[4], bh4[4][4], bl4[4][4];
      ldm4(ql4, sb + oQL + ((wm * 16 + lr) * 72 + ks * 16 + lc) * 2);
#pragma unroll
      for (int ni = 0; ni < 4; ni++) {
        uint32_t o = ((wx * 64 + ni * 16 + lr) * 72 + ks * 16 + lc) * 2;
        ldm4(bh4[ni], bK + o);
        ldm4(bl4[ni], bKl + o);
      }
#pragma unroll
      for (int nj = 0; nj < 8; nj++) {
        uint32_t bb2[2] = {bh4[nj >> 1][nj & 1], bh4[nj >> 1][(nj & 1) + 2]};
        uint32_t bl2[2] = {bl4[nj >> 1][nj & 1], bl4[nj >> 1][(nj & 1) + 2]};
        mma_bf(sacc[nj], qh[ks], bb2);
        mma_bf(sacc[nj], qh[ks], bl2);
        mma_bf(sacc[nj], ql4, bb2);
      }
    }

    // epilogue: mask (fast path), exp, fp32->gmem, rowsum, pack
    uint32_t eab[8][2];
    uint32_t wmA[2], wmB[2];
#pragma unroll
    for (int hf = 0; hf < 2; hf++) {
      int qr = q0 + wm * 16 + r0 + hf * 8;
      size_t mo = ((size_t)b * L + qr) * 64 + kc * 4 + wx * 2;
      wmA[hf] = g_mbits[mo];
      wmB[hf] = g_mbits[mo + 1];
    }
#pragma unroll
    for (int nj = 0; nj < 8; nj++)
#pragma unroll
      for (int hf = 0; hf < 2; hf++) {
        int qr = q0 + wm * 16 + r0 + hf * 8;
        int colL = wx * 64 + nj * 8 + c0;
        uint32_t w = (nj < 4) ? wmA[hf] : wmB[hf];
        float e0, e1;
        if (w == 0xFFFFFFFFu) {
          e0 = __expf(fminf(sacc[nj][hf * 2], 60.f));
          e1 = __expf(fminf(sacc[nj][hf * 2 + 1], 60.f));
        } else {
          int bp = (nj & 3) * 8 + c0;
          e0 = ((w >> bp) & 1u) ? __expf(fminf(sacc[nj][hf * 2], 60.f)) : 0.f;
          e1 = ((w >> (bp + 1)) & 1u) ? __expf(fminf(sacc[nj][hf * 2 + 1], 60.f)) : 0.f;
        }
        rs[hf] += e0 + e1;
        *(float2*)(attnE + ((size_t)bh * L + qr) * L + kc * 128 + colL) = make_float2(e0, e1);
        eab[nj][hf] = packbf(e0, e1);
      }

    // O += E @ Vt
#pragma unroll
    for (int kt = 0; kt < 4; kt++) {
      uint32_t vb[4][4];
#pragma unroll
      for (int ni = 0; ni < 4; ni++)
        ldm4(vb[ni], bV + ((ni * 16 + lr) * 136 + wx * 64 + kt * 16 + lc) * 2);
      uint32_t ae[4] = {eab[2 * kt][0], eab[2 * kt][1],
                        eab[2 * kt + 1][0], eab[2 * kt + 1][1]};
#pragma unroll
      for (int njO = 0; njO < 8; njO++) {
        uint32_t bb2[2] = {vb[njO >> 1][njO & 1], vb[njO >> 1][(njO & 1) + 2]};
        mma_bf(acc_o[njO], ae, bb2);
      }
    }
    __syncthreads();  // protect double buffer before next-next issue
  }

  // rowsum reduce -> sinv
  float* ps = (float*)(sm + oPS);
  float* sinv = (float*)(sm + oSI);
#pragma unroll
  for (int j = 0; j < 2; j++) {
    float v = rs[j];
    v += __shfl_xor_sync(0xffffffffu, v, 1);
    v += __shfl_xor_sync(0xffffffffu, v, 2);
    if ((lane & 3) == 0) ps[wx * 128 + wm * 16 + j * 8 + r0] = v;
  }
  __syncthreads();
  if (tid < 128) {
    float t = ps[tid] + ps[128 + tid];
    sinv[tid] = (t > 0.f) ? 1.f / t : 0.f;
  }
  __syncthreads();

  // cross-wx O reduction via RED, then normalized store
  float* red = (float*)(sm + oRED);
  if (wx == 1) {
#pragma unroll
    for (int hf = 0; hf < 2; hf++) {
      int rl = wm * 16 + r0 + hf * 8;
#pragma unroll
      for (int njO = 0; njO < 8; njO++)
        *(float2*)&red[rl * 68 + njO * 8 + c0] =
            make_float2(acc_o[njO][hf * 2], acc_o[njO][hf * 2 + 1]);
    }
  }
  __syncthreads();
  if (wx == 0) {
#pragma unroll
    for (int hf = 0; hf < 2; hf++) {
      int rl = wm * 16 + r0 + hf * 8;
      float iv = sinv[rl];
      int qr = q0 + rl;
#pragma unroll
      for (int njO = 0; njO < 8; njO++) {
        float2 p = *(float2*)&red[rl * 68 + njO * 8 + c0];
        *(uint32_t*)(g_Obf + ((size_t)b * L + qr) * 1024 + h * 64 + njO * 8 + c0) =
            packbf((acc_o[njO][hf * 2] + p.x) * iv,
                   (acc_o[njO][hf * 2 + 1] + p.y) * iv);
      }
    }
  }

  // fold attn normalization — COALESCED: consecutive threads touch
  // consecutive float4s (was: 2KB lane stride = one 32B sector per 16B access)
  float4* base = (float4*)(attnE + ((size_t)bh * L + q0) * L);
#pragma unroll 4
  for (int it = 0; it < 128; it++) {
    int idx = tid + it * 512;            // 0 .. 65535
    int rr = idx >> 9, cc = idx & 511;   // row 0..127, col4 0..511
    float iv2 = sinv[rr];
    float4* np = base + (size_t)rr * 512 + cc;
    float4 v = *np;
    v.x *= iv2; v.y *= iv2; v.z *= iv2; v.w *= iv2;
    *np = v;
  }
}

// ---- LayerNorm ----
__global__ void __launch_bounds__(256) ln_kernel(const float* __restrict__ gamma,
    const float* __restrict__ beta, float* __restrict__ out) {
  const int row = blockIdx.x, tid = threadIdx.x;
  const float* x = g_X + (size_t)row * D;
  float4 v = *(const float4*)&x[tid * 4];
  float s = v.x + v.y + v.z + v.w;
  float s2 = v.x * v.x + v.y * v.y + v.z * v.z + v.w * v.w;
#pragma unroll
  for (int off = 16; off; off >>= 1) {
    s += __shfl_xor_sync(0xffffffffu, s, off);
    s2 += __shfl_xor_sync(0xffffffffu, s2, off);
  }
  __shared__ float ws[8], ws2[8], mean_s, rstd_s;
  int w = tid >> 5, lid = tid & 31;
  if (lid == 0) { ws[w] = s; ws2[w] = s2; }
  __syncthreads();
  if (tid == 0) {
    float S = 0.f, S2 = 0.f;
#pragma unroll
    for (int i = 0; i < 8; i++) { S += ws[i]; S2 += ws2[i]; }
    float mu = S * (1.f / D);
    mean_s = mu;
    rstd_s = rsqrtf(S2 * (1.f / D) - mu * mu + 1e-6f);
  }
  __syncthreads();
  float mu = mean_s, rstd = rstd_s;
  float4 g4 = *(const float4*)&gamma[tid * 4];
  float4 b4 = *(const float4*)&beta[tid * 4];
  *(float4*)&out[(size_t)row * D + tid * 4] = make_float4(
      (v.x - mu) * rstd * g4.x + b4.x, (v.y - mu) * rstd * g4.y + b4.y,
      (v.z - mu) * rstd * g4.z + b4.z, (v.w - mu) * rstd * g4.w + b4.w);
}

extern "C" void kernel_launch(void* const* d_in, const int* in_sizes, int n_in,
                              void* d_out, int out_size) {
  const float* q = (const float*)d_in[0];
  const float* k = (const float*)d_in[1];
  const float* v = (const float*)d_in[2];
  const int* mask = (const int*)d_in[3];
  const float* wq = (const float*)d_in[4];
  const float* wk = (const float*)d_in[5];
  const float* wv = (const float*)d_in[6];
  const float* wfc = (const float*)d_in[7];
  const float* lng = (const float*)d_in[8];
  const float* lnb = (const float*)d_in[9];
  (void)in_sizes; (void)n_in; (void)out_size;
  float* out = (float*)d_out;
  float* attn = out + OUT_ELEMS;

  __nv_bfloat16 *p_vbf, *p_wvh, *p_wfh, *p_obf;
  uint32_t* p_mb;
  cudaGetSymbolAddress((void**)&p_vbf, g_vbf);
  cudaGetSymbolAddress((void**)&p_wvh, g_wvh);
  cudaGetSymbolAddress((void**)&p_wfh, g_wfh);
  cudaGetSymbolAddress((void**)&p_obf, g_Obf);
  cudaGetSymbolAddress((void**)&p_mb, g_mbits);

  cudaFuncSetAttribute(mmQK, cudaFuncAttributeMaxDynamicSharedMemorySize, 81920);
  cudaFuncSetAttribute(mmk<2>, cudaFuncAttributeMaxDynamicSharedMemorySize, 40960);
  cudaFuncSetAttribute(mmk<3>, cudaFuncAttributeMaxDynamicSharedMemorySize, 40960);
  cudaFuncSetAttribute(attn_tc, cudaFuncAttributeMaxDynamicSharedMemorySize, ATTN_SMEM);

  // launch order: attn_tc at index 3 (the observed ncu capture slot)
  prep<<<17408, 256>>>(q, k, v, wq, wk, wv, wfc, mask, p_mb);             // 0
  mmQK<<<dim3(8, 32, 2), 256, 81920>>>();                                 // 1
  mmk<2><<<dim3(8, 32), 256, 40960>>>(p_vbf, p_wvh, nullptr);             // 2
  attn_tc<<<dim3(L / 128, H, B), 512, ATTN_SMEM>>>(attn);                 // 3
  mmk<3><<<dim3(8, 32), 256, 40960>>>(p_obf, p_wfh, q);                   // 4
  ln_kernel<<<M, 256>>>(lng, lnb, out);                                   // 5
}